// round 2
// baseline (speedup 1.0000x reference)
#include <cuda_runtime.h>
#include <cstdint>
#include <math.h>

// MMD loss: B=4096, D=256, N=2B=8192.
// loss = (1/B^2) * sum_{i,j} sign(i,j) * K(i,j),  sign = +1 same block, -1 cross.
// K(i,j) = sum_{m=0..4} exp(-L2_ij / (bw * 2^m)),  bw = (sum L2)/(N^2-N)/4.
// Trick: u = exp(-L2/(16 bw)) -> K = u + u^2 + u^4 + u^8 + u^16 (1 MUFU + 4 FMUL).

#define DDIM 256
#define BK   16
#define BMP  132   // 128 + 4 pad (keeps float4 alignment, kills store conflicts)

__device__ float  g_total[8192 * 256];  // concatenated [src; tgt]
__device__ float  g_sq[8192];           // row squared norms
__device__ float  g_colsum[256];        // column sums (for ||sum x||^2)
__device__ float  g_negc;               // -1/(16*bw)
__device__ double g_accum;              // signed kernel-sum accumulator

// ---------------------------------------------------------------------------
__global__ void k_zero() {
    g_colsum[threadIdx.x] = 0.f;
    if (threadIdx.x == 0) g_accum = 0.0;
}

// ---------------------------------------------------------------------------
// Copy src/tgt into g_total, compute per-row sq norms, accumulate column sums.
// 256 threads/block, 8 warps, each warp handles 8 rows -> 64 rows/block.
__global__ void k_prep(const float* __restrict__ src,
                       const float* __restrict__ tgt, int B) {
    __shared__ float scol[256];
    scol[threadIdx.x] = 0.f;
    __syncthreads();

    const int warp = threadIdx.x >> 5;
    const int lane = threadIdx.x & 31;
    const int rowBase = blockIdx.x * 64 + warp * 8;

    float c0 = 0.f, c1 = 0.f, c2 = 0.f, c3 = 0.f;
    float c4 = 0.f, c5 = 0.f, c6 = 0.f, c7 = 0.f;

    #pragma unroll
    for (int r = 0; r < 8; ++r) {
        const int row = rowBase + r;
        const float* rp = (row < B) ? (src + (size_t)row * DDIM)
                                    : (tgt + (size_t)(row - B) * DDIM);
        float4 v0 = *(const float4*)(rp + lane * 4);
        float4 v1 = *(const float4*)(rp + 128 + lane * 4);
        *(float4*)(g_total + (size_t)row * DDIM + lane * 4)       = v0;
        *(float4*)(g_total + (size_t)row * DDIM + 128 + lane * 4) = v1;

        float ss = v0.x * v0.x + v0.y * v0.y + v0.z * v0.z + v0.w * v0.w
                 + v1.x * v1.x + v1.y * v1.y + v1.z * v1.z + v1.w * v1.w;
        #pragma unroll
        for (int o = 16; o; o >>= 1) ss += __shfl_xor_sync(0xffffffffu, ss, o);
        if (lane == 0) g_sq[row] = ss;

        c0 += v0.x; c1 += v0.y; c2 += v0.z; c3 += v0.w;
        c4 += v1.x; c5 += v1.y; c6 += v1.z; c7 += v1.w;
    }

    atomicAdd(&scol[lane * 4 + 0], c0);
    atomicAdd(&scol[lane * 4 + 1], c1);
    atomicAdd(&scol[lane * 4 + 2], c2);
    atomicAdd(&scol[lane * 4 + 3], c3);
    atomicAdd(&scol[128 + lane * 4 + 0], c4);
    atomicAdd(&scol[128 + lane * 4 + 1], c5);
    atomicAdd(&scol[128 + lane * 4 + 2], c6);
    atomicAdd(&scol[128 + lane * 4 + 3], c7);
    __syncthreads();
    atomicAdd(&g_colsum[threadIdx.x], scol[threadIdx.x]);
}

// ---------------------------------------------------------------------------
// Bandwidth from closed form: sum L2 = 2N*sum(sq) - 2*||colsum||^2.
__global__ void k_bw(int B) {
    const int N = 2 * B;
    __shared__ double sh[256];
    const int t = threadIdx.x;

    double s = 0.0;
    for (int i = t; i < N; i += 256) s += (double)g_sq[i];
    sh[t] = s;
    __syncthreads();
    for (int st = 128; st; st >>= 1) {
        if (t < st) sh[t] += sh[t + st];
        __syncthreads();
    }
    double sumsq = sh[0];
    __syncthreads();

    float c = g_colsum[t];
    sh[t] = (double)c * (double)c;
    __syncthreads();
    for (int st = 128; st; st >>= 1) {
        if (t < st) sh[t] += sh[t + st];
        __syncthreads();
    }
    if (t == 0) {
        double ssq   = sh[0];
        double sumL2 = 2.0 * (double)N * sumsq - 2.0 * ssq;
        double bw    = sumL2 / ((double)N * (double)N - (double)N);
        bw /= 4.0;  // KERNEL_MUL^(KERNEL_NUM//2) = 2^2
        g_negc  = (float)(-1.0 / (16.0 * bw));
        g_accum = 0.0;
    }
}

// ---------------------------------------------------------------------------
// Main tiled kernel: 128x128 tile per block, fused Gaussian epilogue.
// 1D grid over the NT*(NT+1)/2 upper-triangular tiles (no dead CTAs);
// off-diagonal tiles carry weight 2 (symmetry).
__global__ void __launch_bounds__(256) k_mmd(int B, int NT) {
    // decode linear upper-triangular index -> (ti, tj), tj >= ti.
    // idx = ti*NT - ti*(ti-1)/2 + (tj - ti)
    const int idx = blockIdx.x;
    float fn = (float)NT + 0.5f;
    int ti = (int)(fn - sqrtf(fn * fn - 2.0f * (float)idx));
    // fix potential off-by-one from float rounding
    while (ti * NT - (ti * (ti - 1)) / 2 > idx) --ti;
    while ((ti + 1) * NT - ((ti + 1) * ti) / 2 <= idx) ++ti;
    const int tj = ti + (idx - (ti * NT - (ti * (ti - 1)) / 2));

    __shared__ float As[BK * BMP];
    __shared__ float Bs[BK * BMP];
    __shared__ float red[256];

    const int t  = threadIdx.x;
    const int lr = t >> 2;   // load row 0..63
    const int lv = t & 3;    // float4 index within 16-wide k-slab

    const float* Abase = g_total + (size_t)ti * 128 * DDIM;
    const float* Bbase = g_total + (size_t)tj * 128 * DDIM;

    float4 a0 = *(const float4*)(Abase + (size_t)lr * DDIM + lv * 4);
    float4 a1 = *(const float4*)(Abase + (size_t)(lr + 64) * DDIM + lv * 4);
    float4 b0 = *(const float4*)(Bbase + (size_t)lr * DDIM + lv * 4);
    float4 b1 = *(const float4*)(Bbase + (size_t)(lr + 64) * DDIM + lv * 4);

    const int tx = t & 15, ty = t >> 4;
    float acc[8][8];
    #pragma unroll
    for (int i = 0; i < 8; ++i)
        #pragma unroll
        for (int j = 0; j < 8; ++j) acc[i][j] = 0.f;

    for (int kb = 0; kb < DDIM; kb += BK) {
        __syncthreads();
        // scatter current float4s into k-major smem (k = lv*4 + c)
        As[(lv * 4 + 0) * BMP + lr]      = a0.x;
        As[(lv * 4 + 1) * BMP + lr]      = a0.y;
        As[(lv * 4 + 2) * BMP + lr]      = a0.z;
        As[(lv * 4 + 3) * BMP + lr]      = a0.w;
        As[(lv * 4 + 0) * BMP + lr + 64] = a1.x;
        As[(lv * 4 + 1) * BMP + lr + 64] = a1.y;
        As[(lv * 4 + 2) * BMP + lr + 64] = a1.z;
        As[(lv * 4 + 3) * BMP + lr + 64] = a1.w;
        Bs[(lv * 4 + 0) * BMP + lr]      = b0.x;
        Bs[(lv * 4 + 1) * BMP + lr]      = b0.y;
        Bs[(lv * 4 + 2) * BMP + lr]      = b0.z;
        Bs[(lv * 4 + 3) * BMP + lr]      = b0.w;
        Bs[(lv * 4 + 0) * BMP + lr + 64] = b1.x;
        Bs[(lv * 4 + 1) * BMP + lr + 64] = b1.y;
        Bs[(lv * 4 + 2) * BMP + lr + 64] = b1.z;
        Bs[(lv * 4 + 3) * BMP + lr + 64] = b1.w;
        __syncthreads();

        if (kb + BK < DDIM) {  // prefetch next slab into registers
            a0 = *(const float4*)(Abase + (size_t)lr * DDIM + kb + BK + lv * 4);
            a1 = *(const float4*)(Abase + (size_t)(lr + 64) * DDIM + kb + BK + lv * 4);
            b0 = *(const float4*)(Bbase + (size_t)lr * DDIM + kb + BK + lv * 4);
            b1 = *(const float4*)(Bbase + (size_t)(lr + 64) * DDIM + kb + BK + lv * 4);
        }

        #pragma unroll
        for (int k = 0; k < BK; ++k) {
            float4 ar0 = *(const float4*)&As[k * BMP + ty * 4];
            float4 ar1 = *(const float4*)&As[k * BMP + ty * 4 + 64];
            float4 br0 = *(const float4*)&Bs[k * BMP + tx * 4];
            float4 br1 = *(const float4*)&Bs[k * BMP + tx * 4 + 64];
            float av[8] = {ar0.x, ar0.y, ar0.z, ar0.w, ar1.x, ar1.y, ar1.z, ar1.w};
            float bv[8] = {br0.x, br0.y, br0.z, br0.w, br1.x, br1.y, br1.z, br1.w};
            #pragma unroll
            for (int i = 0; i < 8; ++i)
                #pragma unroll
                for (int j = 0; j < 8; ++j)
                    acc[i][j] = fmaf(av[i], bv[j], acc[i][j]);
        }
    }

    // -------- fused epilogue: L2 -> sum of 5 Gaussian kernels --------
    const float negc = g_negc;
    float sqa[8], sqb[8];
    #pragma unroll
    for (int i = 0; i < 8; ++i) {
        int li = (i < 4) ? (ty * 4 + i) : (64 + ty * 4 + (i - 4));
        int lj = (i < 4) ? (tx * 4 + i) : (64 + tx * 4 + (i - 4));
        sqa[i] = g_sq[ti * 128 + li];
        sqb[i] = g_sq[tj * 128 + lj];
    }

    float tsum = 0.f;
    #pragma unroll
    for (int i = 0; i < 8; ++i) {
        #pragma unroll
        for (int j = 0; j < 8; ++j) {
            float l2 = fmaf(-2.f, acc[i][j], sqa[i] + sqb[j]);
            float u  = __expf(l2 * negc);          // exp(-L2/(16 bw))
            float u2 = u * u, u4 = u2 * u2, u8 = u4 * u4, u16 = u8 * u8;
            tsum += (u + u2) + (u4 + u8) + u16;
        }
    }

    red[t] = tsum;
    __syncthreads();
    #pragma unroll
    for (int st = 128; st; st >>= 1) {
        if (t < st) red[t] += red[t + st];
        __syncthreads();
    }
    if (t == 0) {
        bool  si   = (ti * 128) < B;
        bool  sj   = (tj * 128) < B;
        float w    = (ti == tj) ? 1.f : 2.f;
        float sgnw = (si == sj) ? w : -w;
        atomicAdd(&g_accum, (double)(red[0] * sgnw));
    }
}

// ---------------------------------------------------------------------------
__global__ void k_final(float* out, int B) {
    out[0] = (float)(g_accum / ((double)B * (double)B));
}

// ---------------------------------------------------------------------------
extern "C" void kernel_launch(void* const* d_in, const int* in_sizes, int n_in,
                              void* d_out, int out_size) {
    const float* src = (const float*)d_in[0];
    const float* tgt = (const float*)d_in[1];
    const int B = in_sizes[0] / DDIM;   // 4096
    const int N = 2 * B;                // 8192
    const int NT = N / 128;             // 64 tiles per dim

    k_zero<<<1, 256>>>();
    k_prep<<<N / 64, 256>>>(src, tgt, B);
    k_bw<<<1, 256>>>(B);
    const int ntri = NT * (NT + 1) / 2; // 2080 upper-triangular tiles
    k_mmd<<<ntri, 256>>>(B, NT);
    k_final<<<1, 1>>>((float*)d_out, B);
}

// round 3
// speedup vs baseline: 1.0501x; 1.0501x over previous
#include <cuda_runtime.h>
#include <cstdint>
#include <math.h>

// MMD loss: B=4096, D=256, N=2B=8192.
// loss = (1/B^2) * sum_{i,j} sign(i,j) * K(i,j),  sign = +1 same block, -1 cross.
// K(i,j) = sum_{m=0..4} exp(-L2_ij / (bw * 2^m)),  bw = (sum L2)/(N^2-N)/4.
// u = exp(-L2/(16 bw)) -> K = u + u^2 + u^4 + u^8 + u^16 (1 MUFU + 4 FMUL).
// GEMM inner loop uses packed fma.rn.f32x2 (2 FMA / instruction).

#define DDIM 256
#define BK   16
#define BMP  132   // 128 + 4 pad (keeps 16B alignment: 132*4=528=16*33)

__device__ float  g_total[8192 * 256];  // concatenated [src; tgt]
__device__ float  g_sq[8192];           // row squared norms
__device__ float  g_colsum[256];        // column sums (for ||sum x||^2)
__device__ float  g_negc;               // -1/(16*bw)
__device__ double g_accum;              // signed kernel-sum accumulator

// ---- packed f32x2 helpers --------------------------------------------------
__device__ __forceinline__ unsigned long long f2_dup(float x) {
    unsigned long long r;
    unsigned int u = __float_as_uint(x);
    asm("mov.b64 %0, {%1, %1};" : "=l"(r) : "r"(u));
    return r;
}
__device__ __forceinline__ void f2_fma(unsigned long long& d,
                                       unsigned long long a,
                                       unsigned long long b) {
    asm("fma.rn.f32x2 %0, %1, %2, %0;" : "+l"(d) : "l"(a), "l"(b));
}
__device__ __forceinline__ void f2_unpack(unsigned long long v, float& lo, float& hi) {
    unsigned int ulo, uhi;
    asm("mov.b64 {%0, %1}, %2;" : "=r"(ulo), "=r"(uhi) : "l"(v));
    lo = __uint_as_float(ulo);
    hi = __uint_as_float(uhi);
}

// ---------------------------------------------------------------------------
__global__ void k_zero() {
    g_colsum[threadIdx.x] = 0.f;
    if (threadIdx.x == 0) g_accum = 0.0;
}

// ---------------------------------------------------------------------------
// Copy src/tgt into g_total, compute per-row sq norms, accumulate column sums.
__global__ void k_prep(const float* __restrict__ src,
                       const float* __restrict__ tgt, int B) {
    __shared__ float scol[256];
    scol[threadIdx.x] = 0.f;
    __syncthreads();

    const int warp = threadIdx.x >> 5;
    const int lane = threadIdx.x & 31;
    const int rowBase = blockIdx.x * 64 + warp * 8;

    float c0 = 0.f, c1 = 0.f, c2 = 0.f, c3 = 0.f;
    float c4 = 0.f, c5 = 0.f, c6 = 0.f, c7 = 0.f;

    #pragma unroll
    for (int r = 0; r < 8; ++r) {
        const int row = rowBase + r;
        const float* rp = (row < B) ? (src + (size_t)row * DDIM)
                                    : (tgt + (size_t)(row - B) * DDIM);
        float4 v0 = *(const float4*)(rp + lane * 4);
        float4 v1 = *(const float4*)(rp + 128 + lane * 4);
        *(float4*)(g_total + (size_t)row * DDIM + lane * 4)       = v0;
        *(float4*)(g_total + (size_t)row * DDIM + 128 + lane * 4) = v1;

        float ss = v0.x * v0.x + v0.y * v0.y + v0.z * v0.z + v0.w * v0.w
                 + v1.x * v1.x + v1.y * v1.y + v1.z * v1.z + v1.w * v1.w;
        #pragma unroll
        for (int o = 16; o; o >>= 1) ss += __shfl_xor_sync(0xffffffffu, ss, o);
        if (lane == 0) g_sq[row] = ss;

        c0 += v0.x; c1 += v0.y; c2 += v0.z; c3 += v0.w;
        c4 += v1.x; c5 += v1.y; c6 += v1.z; c7 += v1.w;
    }

    atomicAdd(&scol[lane * 4 + 0], c0);
    atomicAdd(&scol[lane * 4 + 1], c1);
    atomicAdd(&scol[lane * 4 + 2], c2);
    atomicAdd(&scol[lane * 4 + 3], c3);
    atomicAdd(&scol[128 + lane * 4 + 0], c4);
    atomicAdd(&scol[128 + lane * 4 + 1], c5);
    atomicAdd(&scol[128 + lane * 4 + 2], c6);
    atomicAdd(&scol[128 + lane * 4 + 3], c7);
    __syncthreads();
    atomicAdd(&g_colsum[threadIdx.x], scol[threadIdx.x]);
}

// ---------------------------------------------------------------------------
// Bandwidth from closed form: sum L2 = 2N*sum(sq) - 2*||colsum||^2.
__global__ void k_bw(int B) {
    const int N = 2 * B;
    __shared__ double sh[256];
    const int t = threadIdx.x;

    double s = 0.0;
    for (int i = t; i < N; i += 256) s += (double)g_sq[i];
    sh[t] = s;
    __syncthreads();
    for (int st = 128; st; st >>= 1) {
        if (t < st) sh[t] += sh[t + st];
        __syncthreads();
    }
    double sumsq = sh[0];
    __syncthreads();

    float c = g_colsum[t];
    sh[t] = (double)c * (double)c;
    __syncthreads();
    for (int st = 128; st; st >>= 1) {
        if (t < st) sh[t] += sh[t + st];
        __syncthreads();
    }
    if (t == 0) {
        double ssq   = sh[0];
        double sumL2 = 2.0 * (double)N * sumsq - 2.0 * ssq;
        double bw    = sumL2 / ((double)N * (double)N - (double)N);
        bw /= 4.0;  // KERNEL_MUL^(KERNEL_NUM//2) = 2^2
        g_negc  = (float)(-1.0 / (16.0 * bw));
        g_accum = 0.0;
    }
}

// ---------------------------------------------------------------------------
// Main tiled kernel: 128x128 tile per block, fused Gaussian epilogue.
// 1D grid over the NT*(NT+1)/2 upper-triangular tiles; off-diag weight 2.
__global__ void __launch_bounds__(256) k_mmd(int B, int NT) {
    // decode linear upper-triangular index -> (ti, tj), tj >= ti.
    const int idx = blockIdx.x;
    float fn = (float)NT + 0.5f;
    int ti = (int)(fn - sqrtf(fn * fn - 2.0f * (float)idx));
    while (ti * NT - (ti * (ti - 1)) / 2 > idx) --ti;
    while ((ti + 1) * NT - ((ti + 1) * ti) / 2 <= idx) ++ti;
    const int tj = ti + (idx - (ti * NT - (ti * (ti - 1)) / 2));

    __shared__ float As[BK * BMP];
    __shared__ float Bs[BK * BMP];
    __shared__ float red[256];

    const int t  = threadIdx.x;
    const int lr = t >> 2;   // load row 0..63
    const int lv = t & 3;    // float4 index within 16-wide k-slab

    const float* Abase = g_total + (size_t)ti * 128 * DDIM;
    const float* Bbase = g_total + (size_t)tj * 128 * DDIM;

    float4 a0 = *(const float4*)(Abase + (size_t)lr * DDIM + lv * 4);
    float4 a1 = *(const float4*)(Abase + (size_t)(lr + 64) * DDIM + lv * 4);
    float4 b0 = *(const float4*)(Bbase + (size_t)lr * DDIM + lv * 4);
    float4 b1 = *(const float4*)(Bbase + (size_t)(lr + 64) * DDIM + lv * 4);

    const int tx = t & 15, ty = t >> 4;

    // acc2[i][jp]: packed pair (j = jp*2, jp*2+1) in epilogue j-order
    unsigned long long acc2[8][4];
    #pragma unroll
    for (int i = 0; i < 8; ++i)
        #pragma unroll
        for (int j = 0; j < 4; ++j) acc2[i][j] = 0ull;

    for (int kb = 0; kb < DDIM; kb += BK) {
        __syncthreads();
        As[(lv * 4 + 0) * BMP + lr]      = a0.x;
        As[(lv * 4 + 1) * BMP + lr]      = a0.y;
        As[(lv * 4 + 2) * BMP + lr]      = a0.z;
        As[(lv * 4 + 3) * BMP + lr]      = a0.w;
        As[(lv * 4 + 0) * BMP + lr + 64] = a1.x;
        As[(lv * 4 + 1) * BMP + lr + 64] = a1.y;
        As[(lv * 4 + 2) * BMP + lr + 64] = a1.z;
        As[(lv * 4 + 3) * BMP + lr + 64] = a1.w;
        Bs[(lv * 4 + 0) * BMP + lr]      = b0.x;
        Bs[(lv * 4 + 1) * BMP + lr]      = b0.y;
        Bs[(lv * 4 + 2) * BMP + lr]      = b0.z;
        Bs[(lv * 4 + 3) * BMP + lr]      = b0.w;
        Bs[(lv * 4 + 0) * BMP + lr + 64] = b1.x;
        Bs[(lv * 4 + 1) * BMP + lr + 64] = b1.y;
        Bs[(lv * 4 + 2) * BMP + lr + 64] = b1.z;
        Bs[(lv * 4 + 3) * BMP + lr + 64] = b1.w;
        __syncthreads();

        if (kb + BK < DDIM) {  // prefetch next slab into registers
            a0 = *(const float4*)(Abase + (size_t)lr * DDIM + kb + BK + lv * 4);
            a1 = *(const float4*)(Abase + (size_t)(lr + 64) * DDIM + kb + BK + lv * 4);
            b0 = *(const float4*)(Bbase + (size_t)lr * DDIM + kb + BK + lv * 4);
            b1 = *(const float4*)(Bbase + (size_t)(lr + 64) * DDIM + kb + BK + lv * 4);
        }

        #pragma unroll
        for (int k = 0; k < BK; ++k) {
            // B operands read as 64-bit pairs: LDS.128 -> aligned reg pairs, no packing
            ulonglong2 bb0 = *(const ulonglong2*)&Bs[k * BMP + tx * 4];
            ulonglong2 bb1 = *(const ulonglong2*)&Bs[k * BMP + tx * 4 + 64];
            unsigned long long bp[4] = {bb0.x, bb0.y, bb1.x, bb1.y};

            float4 ar0 = *(const float4*)&As[k * BMP + ty * 4];
            float4 ar1 = *(const float4*)&As[k * BMP + ty * 4 + 64];
            float av[8] = {ar0.x, ar0.y, ar0.z, ar0.w, ar1.x, ar1.y, ar1.z, ar1.w};

            unsigned long long ap[8];
            #pragma unroll
            for (int i = 0; i < 8; ++i) ap[i] = f2_dup(av[i]);

            #pragma unroll
            for (int i = 0; i < 8; ++i)
                #pragma unroll
                for (int j = 0; j < 4; ++j)
                    f2_fma(acc2[i][j], ap[i], bp[j]);
        }
    }

    // -------- fused epilogue: L2 -> sum of 5 Gaussian kernels --------
    const float negc = g_negc;
    float sqa[8], sqb[8];
    #pragma unroll
    for (int i = 0; i < 8; ++i) {
        int li = (i < 4) ? (ty * 4 + i) : (64 + ty * 4 + (i - 4));
        int lj = (i < 4) ? (tx * 4 + i) : (64 + tx * 4 + (i - 4));
        sqa[i] = g_sq[ti * 128 + li];
        sqb[i] = g_sq[tj * 128 + lj];
    }

    float tsum = 0.f;
    #pragma unroll
    for (int i = 0; i < 8; ++i) {
        #pragma unroll
        for (int jp = 0; jp < 4; ++jp) {
            float d0, d1;
            f2_unpack(acc2[i][jp], d0, d1);
            int j0 = jp * 2, j1 = jp * 2 + 1;
            {
                float l2 = fmaf(-2.f, d0, sqa[i] + sqb[j0]);
                float u  = __expf(l2 * negc);
                float u2 = u * u, u4 = u2 * u2, u8 = u4 * u4, u16 = u8 * u8;
                tsum += (u + u2) + (u4 + u8) + u16;
            }
            {
                float l2 = fmaf(-2.f, d1, sqa[i] + sqb[j1]);
                float u  = __expf(l2 * negc);
                float u2 = u * u, u4 = u2 * u2, u8 = u4 * u4, u16 = u8 * u8;
                tsum += (u + u2) + (u4 + u8) + u16;
            }
        }
    }

    red[t] = tsum;
    __syncthreads();
    #pragma unroll
    for (int st = 128; st; st >>= 1) {
        if (t < st) red[t] += red[t + st];
        __syncthreads();
    }
    if (t == 0) {
        bool  si   = (ti * 128) < B;
        bool  sj   = (tj * 128) < B;
        float w    = (ti == tj) ? 1.f : 2.f;
        float sgnw = (si == sj) ? w : -w;
        atomicAdd(&g_accum, (double)(red[0] * sgnw));
    }
}

// ---------------------------------------------------------------------------
__global__ void k_final(float* out, int B) {
    out[0] = (float)(g_accum / ((double)B * (double)B));
}

// ---------------------------------------------------------------------------
extern "C" void kernel_launch(void* const* d_in, const int* in_sizes, int n_in,
                              void* d_out, int out_size) {
    const float* src = (const float*)d_in[0];
    const float* tgt = (const float*)d_in[1];
    const int B = in_sizes[0] / DDIM;   // 4096
    const int N = 2 * B;                // 8192
    const int NT = N / 128;             // 64 tiles per dim

    k_zero<<<1, 256>>>();
    k_prep<<<N / 64, 256>>>(src, tgt, B);
    k_bw<<<1, 256>>>(B);
    const int ntri = NT * (NT + 1) / 2; // 2080 upper-triangular tiles
    k_mmd<<<ntri, 256>>>(B, NT);
    k_final<<<1, 1>>>((float*)d_out, B);
}

// round 5
// speedup vs baseline: 3.8930x; 3.7074x over previous
#include <cuda_runtime.h>
#include <cuda_bf16.h>
#include <cstdint>
#include <math.h>

// MMD loss: B=4096, D=256, N=2B=8192.
// loss = (1/B^2) * sum_{i,j} sign(i,j) * K(i,j),  sign = +1 same block, -1 cross.
// K(i,j) = sum_{m=0..4} exp(-L2_ij / (bw*2^m)),  bw = (sum L2)/(N^2-N)/4.
// u = exp2(L2 * negc2), negc2 = -log2(e)/(16 bw) -> K = u+u^2+u^4+u^8+u^16.
// Gram matrix via mma.sync bf16 (HMMA, fp32 accum). Inputs rounded to bf16 once;
// sq-norms/bandwidth computed from the rounded data so L2(i,i) == 0 exactly.

#define DDIM 256
#define BK   32          // k-chunk (bf16) per smem pass; 8 chunks cover K=256
#define RSTRIDE 80       // smem row stride bytes (5*16 -> conflict-free ldmatrix)

__device__ __nv_bfloat16 g_bf16[8192 * 256]; // rounded [src; tgt], row-major
__device__ float  g_sq[8192];                // row squared norms (of bf16 data)
__device__ float  g_colsum[256];             // column sums (of bf16 data)
__device__ float  g_negc2;                   // -log2(e)/(16*bw)
__device__ double g_accum;                   // signed kernel-sum accumulator

// ---------------- helpers ---------------------------------------------------
__device__ __forceinline__ uint32_t smem_u32(const void* p) {
    uint32_t a;
    asm("{ .reg .u64 t; cvta.to.shared.u64 t, %1; cvt.u32.u64 %0, t; }" : "=r"(a) : "l"(p));
    return a;
}
__device__ __forceinline__ void ldsm4(uint32_t* r, uint32_t addr) {
    asm volatile("ldmatrix.sync.aligned.m8n8.x4.shared.b16 {%0,%1,%2,%3}, [%4];"
                 : "=r"(r[0]), "=r"(r[1]), "=r"(r[2]), "=r"(r[3]) : "r"(addr));
}
__device__ __forceinline__ void mma16816(float* c, const uint32_t* a, const uint32_t* b) {
    asm volatile(
        "mma.sync.aligned.m16n8k16.row.col.f32.bf16.bf16.f32 "
        "{%0,%1,%2,%3}, {%4,%5,%6,%7}, {%8,%9}, {%0,%1,%2,%3};"
        : "+f"(c[0]), "+f"(c[1]), "+f"(c[2]), "+f"(c[3])
        : "r"(a[0]), "r"(a[1]), "r"(a[2]), "r"(a[3]), "r"(b[0]), "r"(b[1]));
}
__device__ __forceinline__ float fast_ex2(float x) {
    float r;
    asm("ex2.approx.ftz.f32 %0, %1;" : "=f"(r) : "f"(x));
    return r;
}

// ---------------------------------------------------------------------------
__global__ void k_zero() {
    g_colsum[threadIdx.x] = 0.f;
    if (threadIdx.x == 0) g_accum = 0.0;
}

// ---------------------------------------------------------------------------
// Round inputs to bf16; row sq-norms and column sums FROM THE ROUNDED values.
__global__ void k_prep(const float* __restrict__ src,
                       const float* __restrict__ tgt, int B) {
    __shared__ float scol[256];
    scol[threadIdx.x] = 0.f;
    __syncthreads();

    const int warp = threadIdx.x >> 5;
    const int lane = threadIdx.x & 31;
    const int rowBase = blockIdx.x * 64 + warp * 8;

    float c0 = 0.f, c1 = 0.f, c2 = 0.f, c3 = 0.f;
    float c4 = 0.f, c5 = 0.f, c6 = 0.f, c7 = 0.f;

    #pragma unroll
    for (int r = 0; r < 8; ++r) {
        const int row = rowBase + r;
        const float* rp = (row < B) ? (src + (size_t)row * DDIM)
                                    : (tgt + (size_t)(row - B) * DDIM);
        float4 v0 = *(const float4*)(rp + lane * 4);
        float4 v1 = *(const float4*)(rp + 128 + lane * 4);

        __nv_bfloat162 h0 = __floats2bfloat162_rn(v0.x, v0.y);
        __nv_bfloat162 h1 = __floats2bfloat162_rn(v0.z, v0.w);
        __nv_bfloat162 h2 = __floats2bfloat162_rn(v1.x, v1.y);
        __nv_bfloat162 h3 = __floats2bfloat162_rn(v1.z, v1.w);

        uint2 p0 = make_uint2(*(uint32_t*)&h0, *(uint32_t*)&h1);
        uint2 p1 = make_uint2(*(uint32_t*)&h2, *(uint32_t*)&h3);
        *(uint2*)(g_bf16 + (size_t)row * DDIM + lane * 4)       = p0;
        *(uint2*)(g_bf16 + (size_t)row * DDIM + 128 + lane * 4) = p1;

        float x0 = __low2float(h0), x1 = __high2float(h0);
        float x2 = __low2float(h1), x3 = __high2float(h1);
        float x4 = __low2float(h2), x5 = __high2float(h2);
        float x6 = __low2float(h3), x7 = __high2float(h3);

        float ss = x0*x0 + x1*x1 + x2*x2 + x3*x3 + x4*x4 + x5*x5 + x6*x6 + x7*x7;
        #pragma unroll
        for (int o = 16; o; o >>= 1) ss += __shfl_xor_sync(0xffffffffu, ss, o);
        if (lane == 0) g_sq[row] = ss;

        c0 += x0; c1 += x1; c2 += x2; c3 += x3;
        c4 += x4; c5 += x5; c6 += x6; c7 += x7;
    }

    atomicAdd(&scol[lane * 4 + 0], c0);
    atomicAdd(&scol[lane * 4 + 1], c1);
    atomicAdd(&scol[lane * 4 + 2], c2);
    atomicAdd(&scol[lane * 4 + 3], c3);
    atomicAdd(&scol[128 + lane * 4 + 0], c4);
    atomicAdd(&scol[128 + lane * 4 + 1], c5);
    atomicAdd(&scol[128 + lane * 4 + 2], c6);
    atomicAdd(&scol[128 + lane * 4 + 3], c7);
    __syncthreads();
    atomicAdd(&g_colsum[threadIdx.x], scol[threadIdx.x]);
}

// ---------------------------------------------------------------------------
// Bandwidth: sum L2 = 2N*sum(sq) - 2*||colsum||^2, all from the bf16 dataset.
__global__ void k_bw(int B) {
    const int N = 2 * B;
    __shared__ double sh[256];
    const int t = threadIdx.x;

    double s = 0.0;
    for (int i = t; i < N; i += 256) s += (double)g_sq[i];
    sh[t] = s;
    __syncthreads();
    for (int st = 128; st; st >>= 1) {
        if (t < st) sh[t] += sh[t + st];
        __syncthreads();
    }
    double sumsq = sh[0];
    __syncthreads();

    float c = g_colsum[t];
    sh[t] = (double)c * (double)c;
    __syncthreads();
    for (int st = 128; st; st >>= 1) {
        if (t < st) sh[t] += sh[t + st];
        __syncthreads();
    }
    if (t == 0) {
        double ssq   = sh[0];
        double sumL2 = 2.0 * (double)N * sumsq - 2.0 * ssq;
        double bw    = sumL2 / ((double)N * (double)N - (double)N);
        bw /= 4.0;  // KERNEL_MUL^(KERNEL_NUM//2) = 2^2
        g_negc2 = (float)(-1.4426950408889634 / (16.0 * bw));
        g_accum = 0.0;
    }
}

// ---------------------------------------------------------------------------
// Main kernel: 128x128 Gram tile per CTA via mma.sync bf16; fused epilogue.
// 8 warps, each owns 32 rows x 64 cols (2 x 8 m16n8k16 atoms).
// 1D grid over NT*(NT+1)/2 upper-triangular tiles; off-diag weight 2.
__global__ void __launch_bounds__(256) k_mmd(int B, int NT) {
    __shared__ __align__(16) char sA[128 * RSTRIDE];
    __shared__ __align__(16) char sB[128 * RSTRIDE];
    __shared__ float sqa[128], sqb[128];
    __shared__ float red[256];

    const int t = threadIdx.x;
    const int wid = t >> 5, lane = t & 31;

    // decode linear upper-triangular index -> (ti, tj), tj >= ti.
    const int idx = blockIdx.x;
    float fn = (float)NT + 0.5f;
    int ti = (int)(fn - sqrtf(fn * fn - 2.0f * (float)idx));
    while (ti * NT - (ti * (ti - 1)) / 2 > idx) --ti;
    while ((ti + 1) * NT - ((ti + 1) * ti) / 2 <= idx) ++ti;
    const int tj = ti + (idx - (ti * NT - (ti * (ti - 1)) / 2));

    if (t < 128) sqa[t] = g_sq[ti * 128 + t];
    else         sqb[t - 128] = g_sq[tj * 128 + (t - 128)];

    const __nv_bfloat16* Abase = g_bf16 + (size_t)ti * 128 * DDIM;
    const __nv_bfloat16* Bbase = g_bf16 + (size_t)tj * 128 * DDIM;

    const uint32_t sAu = smem_u32(sA);
    const uint32_t sBu = smem_u32(sB);

    // per-thread ldmatrix source addresses
    const int wrow = (wid & 3) * 32;          // warp row base (M)
    const int wcol = (wid >> 2) * 64;         // warp col base (N)
    // A: x4 tiles = rows(lane&15), k-half(lane>>4)
    const uint32_t aAddr = sAu + (uint32_t)(wrow + (lane & 15)) * RSTRIDE
                               + (uint32_t)((lane >> 4) * 8) * 2;
    // B: x4 tiles = n(lane&7) + 8*((lane>>4)&1), k-half((lane>>3)&1)
    const uint32_t bAddr = sBu + (uint32_t)(wcol + (lane & 7) + ((lane >> 4) & 1) * 8) * RSTRIDE
                               + (uint32_t)(((lane >> 3) & 1) * 8) * 2;

    // global->smem staging: thread covers x = t, t+256 of 512 16B segments
    const int r0 = t >> 2, sg0 = t & 3;            // x = t
    const int r1 = (t + 256) >> 2, sg1 = t & 3;    // x = t+256
    const uint32_t st0 = (uint32_t)r0 * RSTRIDE + (uint32_t)sg0 * 16;
    const uint32_t st1 = (uint32_t)r1 * RSTRIDE + (uint32_t)sg1 * 16;

    float acc[2][8][4];
    #pragma unroll
    for (int m = 0; m < 2; ++m)
        #pragma unroll
        for (int n = 0; n < 8; ++n)
            #pragma unroll
            for (int r = 0; r < 4; ++r) acc[m][n][r] = 0.f;

    // prefetch chunk 0
    uint4 pa0 = *(const uint4*)(Abase + (size_t)r0 * DDIM + sg0 * 8);
    uint4 pa1 = *(const uint4*)(Abase + (size_t)r1 * DDIM + sg1 * 8);
    uint4 pb0 = *(const uint4*)(Bbase + (size_t)r0 * DDIM + sg0 * 8);
    uint4 pb1 = *(const uint4*)(Bbase + (size_t)r1 * DDIM + sg1 * 8);

    #pragma unroll 1
    for (int chunk = 0; chunk < DDIM / BK; ++chunk) {
        __syncthreads();   // previous compute done before overwrite
        *(uint4*)(sA + st0) = pa0;
        *(uint4*)(sA + st1) = pa1;
        *(uint4*)(sB + st0) = pb0;
        *(uint4*)(sB + st1) = pb1;
        __syncthreads();

        if (chunk + 1 < DDIM / BK) {
            const int ko = (chunk + 1) * BK;
            pa0 = *(const uint4*)(Abase + (size_t)r0 * DDIM + ko + sg0 * 8);
            pa1 = *(const uint4*)(Abase + (size_t)r1 * DDIM + ko + sg1 * 8);
            pb0 = *(const uint4*)(Bbase + (size_t)r0 * DDIM + ko + sg0 * 8);
            pb1 = *(const uint4*)(Bbase + (size_t)r1 * DDIM + ko + sg1 * 8);
        }

        #pragma unroll
        for (int ks = 0; ks < 2; ++ks) {           // two k16 steps per chunk
            const uint32_t koff = (uint32_t)(ks * 16) * 2;
            uint32_t af[2][4];
            ldsm4(af[0], aAddr + koff);
            ldsm4(af[1], aAddr + 16 * RSTRIDE + koff);
            uint32_t bf_[4][4];                    // pair p -> n-atoms 2p, 2p+1
            #pragma unroll
            for (int p = 0; p < 4; ++p)
                ldsm4(bf_[p], bAddr + (uint32_t)(p * 16) * RSTRIDE + koff);

            #pragma unroll
            for (int m = 0; m < 2; ++m)
                #pragma unroll
                for (int p = 0; p < 4; ++p) {
                    mma16816(acc[m][2 * p],     af[m], &bf_[p][0]);
                    mma16816(acc[m][2 * p + 1], af[m], &bf_[p][2]);
                }
        }
    }

    // -------- fused epilogue: L2 -> sum of 5 Gaussian kernels --------
    const float negc2 = g_negc2;
    // C[row][col]: row = wrow + m*16 + (lane>>2) + 8*(r>=2); col = wcol + n*8 + (lane&3)*2 + (r&1)
    float sa[4], sb[16];
    #pragma unroll
    for (int m = 0; m < 2; ++m)
        #pragma unroll
        for (int h = 0; h < 2; ++h)
            sa[m * 2 + h] = sqa[wrow + m * 16 + (lane >> 2) + h * 8];
    #pragma unroll
    for (int n = 0; n < 8; ++n) {
        sb[n * 2 + 0] = sqb[wcol + n * 8 + (lane & 3) * 2 + 0];
        sb[n * 2 + 1] = sqb[wcol + n * 8 + (lane & 3) * 2 + 1];
    }

    float tsum = 0.f;
    #pragma unroll
    for (int m = 0; m < 2; ++m)
        #pragma unroll
        for (int n = 0; n < 8; ++n)
            #pragma unroll
            for (int r = 0; r < 4; ++r) {
                float d  = acc[m][n][r];
                float l2 = fmaf(-2.f, d, sa[m * 2 + (r >> 1)] + sb[n * 2 + (r & 1)]);
                float u  = fast_ex2(l2 * negc2);
                float u2 = u * u, u4 = u2 * u2, u8 = u4 * u4, u16 = u8 * u8;
                tsum += (u + u2) + (u4 + u8) + u16;
            }

    red[t] = tsum;
    __syncthreads();
    #pragma unroll
    for (int st = 128; st; st >>= 1) {
        if (t < st) red[t] += red[t + st];
        __syncthreads();
    }
    if (t == 0) {
        bool  si   = (ti * 128) < B;
        bool  sj   = (tj * 128) < B;
        float w    = (ti == tj) ? 1.f : 2.f;
        float sgnw = (si == sj) ? w : -w;
        atomicAdd(&g_accum, (double)(red[0] * sgnw));
    }
}

// ---------------------------------------------------------------------------
__global__ void k_final(float* out, int B) {
    out[0] = (float)(g_accum / ((double)B * (double)B));
}

// ---------------------------------------------------------------------------
extern "C" void kernel_launch(void* const* d_in, const int* in_sizes, int n_in,
                              void* d_out, int out_size) {
    const float* src = (const float*)d_in[0];
    const float* tgt = (const float*)d_in[1];
    const int B = in_sizes[0] / DDIM;   // 4096
    const int N = 2 * B;                // 8192
    const int NT = N / 128;             // 64 tiles per dim

    k_zero<<<1, 256>>>();
    k_prep<<<N / 64, 256>>>(src, tgt, B);
    k_bw<<<1, 256>>>(B);
    const int ntri = NT * (NT + 1) / 2; // 2080 upper-triangular tiles
    k_mmd<<<ntri, 256>>>(B, NT);
    k_final<<<1, 1>>>((float*)d_out, B);
}

// round 6
// speedup vs baseline: 4.1565x; 1.0677x over previous
#include <cuda_runtime.h>
#include <cuda_bf16.h>
#include <cstdint>
#include <math.h>

// MMD loss: B=4096, D=256, N=2B=8192.
// loss = (1/B^2) * sum_{i,j} sign(i,j) * K(i,j),  sign = +1 same block, -1 cross.
// K(i,j) = sum_{m=0..4} exp(-L2_ij / (bw*2^m)),  bw = (sum L2)/(N^2-N)/4.
// u = exp2(L2 * negc2), negc2 = -log2(e)/(16 bw) -> K = u+u^2+u^4+u^8+u^16.
// Gram matrix via mma.sync bf16 (fp32 accum), 64x64 warp tiles, cp.async
// double-buffered staging. Inputs rounded to bf16 once; sq-norms/bandwidth
// computed from the rounded data so L2(i,i) == 0 exactly.

#define DDIM 256
#define BK   32          // k-chunk (bf16) per smem pass; 8 chunks cover K=256
#define RSTRIDE 80       // smem row stride bytes (5*16 -> conflict-free ldmatrix)
#define TILEB (128 * RSTRIDE)   // 10240 bytes per matrix per buffer

__device__ __nv_bfloat16 g_bf16[8192 * 256]; // rounded [src; tgt], row-major
__device__ float  g_sq[8192];                // row squared norms (of bf16 data)
__device__ float  g_colsum[256];             // column sums (of bf16 data)
__device__ float  g_negc2;                   // -log2(e)/(16*bw)
__device__ double g_accum;                   // signed kernel-sum accumulator

// ---------------- helpers ---------------------------------------------------
__device__ __forceinline__ uint32_t smem_u32(const void* p) {
    uint32_t a;
    asm("{ .reg .u64 t; cvta.to.shared.u64 t, %1; cvt.u32.u64 %0, t; }" : "=r"(a) : "l"(p));
    return a;
}
__device__ __forceinline__ void ldsm4(uint32_t* r, uint32_t addr) {
    asm volatile("ldmatrix.sync.aligned.m8n8.x4.shared.b16 {%0,%1,%2,%3}, [%4];"
                 : "=r"(r[0]), "=r"(r[1]), "=r"(r[2]), "=r"(r[3]) : "r"(addr));
}
__device__ __forceinline__ void mma16816(float* c, const uint32_t* a, const uint32_t* b) {
    asm volatile(
        "mma.sync.aligned.m16n8k16.row.col.f32.bf16.bf16.f32 "
        "{%0,%1,%2,%3}, {%4,%5,%6,%7}, {%8,%9}, {%0,%1,%2,%3};"
        : "+f"(c[0]), "+f"(c[1]), "+f"(c[2]), "+f"(c[3])
        : "r"(a[0]), "r"(a[1]), "r"(a[2]), "r"(a[3]), "r"(b[0]), "r"(b[1]));
}
__device__ __forceinline__ void cp16(uint32_t dst, const void* src) {
    asm volatile("cp.async.cg.shared.global [%0], [%1], 16;" :: "r"(dst), "l"(src));
}
#define CP_COMMIT() asm volatile("cp.async.commit_group;" ::: "memory")
#define CP_WAIT(n)  asm volatile("cp.async.wait_group %0;" :: "n"(n) : "memory")

__device__ __forceinline__ float fast_ex2(float x) {
    float r;
    asm("ex2.approx.ftz.f32 %0, %1;" : "=f"(r) : "f"(x));
    return r;
}

// ---------------------------------------------------------------------------
__global__ void k_zero() {
    g_colsum[threadIdx.x] = 0.f;
    if (threadIdx.x == 0) g_accum = 0.0;
}

// ---------------------------------------------------------------------------
// Round inputs to bf16; row sq-norms and column sums FROM THE ROUNDED values.
__global__ void k_prep(const float* __restrict__ src,
                       const float* __restrict__ tgt, int B) {
    __shared__ float scol[256];
    scol[threadIdx.x] = 0.f;
    __syncthreads();

    const int warp = threadIdx.x >> 5;
    const int lane = threadIdx.x & 31;
    const int rowBase = blockIdx.x * 64 + warp * 8;

    float c0 = 0.f, c1 = 0.f, c2 = 0.f, c3 = 0.f;
    float c4 = 0.f, c5 = 0.f, c6 = 0.f, c7 = 0.f;

    #pragma unroll
    for (int r = 0; r < 8; ++r) {
        const int row = rowBase + r;
        const float* rp = (row < B) ? (src + (size_t)row * DDIM)
                                    : (tgt + (size_t)(row - B) * DDIM);
        float4 v0 = *(const float4*)(rp + lane * 4);
        float4 v1 = *(const float4*)(rp + 128 + lane * 4);

        __nv_bfloat162 h0 = __floats2bfloat162_rn(v0.x, v0.y);
        __nv_bfloat162 h1 = __floats2bfloat162_rn(v0.z, v0.w);
        __nv_bfloat162 h2 = __floats2bfloat162_rn(v1.x, v1.y);
        __nv_bfloat162 h3 = __floats2bfloat162_rn(v1.z, v1.w);

        uint2 p0 = make_uint2(*(uint32_t*)&h0, *(uint32_t*)&h1);
        uint2 p1 = make_uint2(*(uint32_t*)&h2, *(uint32_t*)&h3);
        *(uint2*)(g_bf16 + (size_t)row * DDIM + lane * 4)       = p0;
        *(uint2*)(g_bf16 + (size_t)row * DDIM + 128 + lane * 4) = p1;

        float x0 = __low2float(h0), x1 = __high2float(h0);
        float x2 = __low2float(h1), x3 = __high2float(h1);
        float x4 = __low2float(h2), x5 = __high2float(h2);
        float x6 = __low2float(h3), x7 = __high2float(h3);

        float ss = x0*x0 + x1*x1 + x2*x2 + x3*x3 + x4*x4 + x5*x5 + x6*x6 + x7*x7;
        #pragma unroll
        for (int o = 16; o; o >>= 1) ss += __shfl_xor_sync(0xffffffffu, ss, o);
        if (lane == 0) g_sq[row] = ss;

        c0 += x0; c1 += x1; c2 += x2; c3 += x3;
        c4 += x4; c5 += x5; c6 += x6; c7 += x7;
    }

    atomicAdd(&scol[lane * 4 + 0], c0);
    atomicAdd(&scol[lane * 4 + 1], c1);
    atomicAdd(&scol[lane * 4 + 2], c2);
    atomicAdd(&scol[lane * 4 + 3], c3);
    atomicAdd(&scol[128 + lane * 4 + 0], c4);
    atomicAdd(&scol[128 + lane * 4 + 1], c5);
    atomicAdd(&scol[128 + lane * 4 + 2], c6);
    atomicAdd(&scol[128 + lane * 4 + 3], c7);
    __syncthreads();
    atomicAdd(&g_colsum[threadIdx.x], scol[threadIdx.x]);
}

// ---------------------------------------------------------------------------
// Bandwidth: sum L2 = 2N*sum(sq) - 2*||colsum||^2, all from the bf16 dataset.
__global__ void k_bw(int B) {
    const int N = 2 * B;
    __shared__ double sh[256];
    const int t = threadIdx.x;

    double s = 0.0;
    for (int i = t; i < N; i += 256) s += (double)g_sq[i];
    sh[t] = s;
    __syncthreads();
    for (int st = 128; st; st >>= 1) {
        if (t < st) sh[t] += sh[t + st];
        __syncthreads();
    }
    double sumsq = sh[0];
    __syncthreads();

    float c = g_colsum[t];
    sh[t] = (double)c * (double)c;
    __syncthreads();
    for (int st = 128; st; st >>= 1) {
        if (t < st) sh[t] += sh[t + st];
        __syncthreads();
    }
    if (t == 0) {
        double ssq   = sh[0];
        double sumL2 = 2.0 * (double)N * sumsq - 2.0 * ssq;
        double bw    = sumL2 / ((double)N * (double)N - (double)N);
        bw /= 4.0;  // KERNEL_MUL^(KERNEL_NUM//2) = 2^2
        g_negc2 = (float)(-1.4426950408889634 / (16.0 * bw));
        g_accum = 0.0;
    }
}

// ---------------------------------------------------------------------------
// Main kernel: 128x128 Gram tile per CTA via mma.sync bf16; fused epilogue.
// 4 warps (2x2), each owns 64x64 (4 x 8 m16n8k16 atoms, 128 fp32 accums).
// cp.async double-buffered k-chunks. 1D grid over upper-triangular tiles.
__global__ void __launch_bounds__(128, 2) k_mmd(int B, int NT) {
    // [A buf0][A buf1][B buf0][B buf1]
    __shared__ __align__(16) char sMem[4 * TILEB];
    __shared__ float sqa[128], sqb[128];
    __shared__ float red[128];

    const int t = threadIdx.x;
    const int wid = t >> 5, lane = t & 31;

    // decode linear upper-triangular index -> (ti, tj), tj >= ti.
    const int idx = blockIdx.x;
    float fn = (float)NT + 0.5f;
    int ti = (int)(fn - sqrtf(fn * fn - 2.0f * (float)idx));
    while (ti * NT - (ti * (ti - 1)) / 2 > idx) --ti;
    while ((ti + 1) * NT - ((ti + 1) * ti) / 2 <= idx) ++ti;
    const int tj = ti + (idx - (ti * NT - (ti * (ti - 1)) / 2));

    if (t < 128) {
        sqa[t] = g_sq[ti * 128 + t];
        sqb[t] = g_sq[tj * 128 + t];
    }

    const __nv_bfloat16* Abase = g_bf16 + (size_t)ti * 128 * DDIM;
    const __nv_bfloat16* Bbase = g_bf16 + (size_t)tj * 128 * DDIM;

    const uint32_t sAu = smem_u32(sMem);            // + buf*TILEB
    const uint32_t sBu = sAu + 2 * TILEB;           // + buf*TILEB

    // warp tile: rows (wid&1)*64, cols (wid>>1)*64
    const int wrow = (wid & 1) * 64;
    const int wcol = (wid >> 1) * 64;
    // ldmatrix base addrs (buffer 0); A x4: rows lane&15, k-half lane>>4
    const uint32_t aAddr = sAu + (uint32_t)(wrow + (lane & 15)) * RSTRIDE
                               + (uint32_t)((lane >> 4) * 16);
    // B x4: n(lane&7) + 8*((lane>>4)&1), k-half (lane>>3)&1
    const uint32_t bAddr = sBu + (uint32_t)(wcol + (lane & 7) + ((lane >> 4) & 1) * 8) * RSTRIDE
                               + (uint32_t)(((lane >> 3) & 1) * 16);

    float acc[4][8][4];
    #pragma unroll
    for (int m = 0; m < 4; ++m)
        #pragma unroll
        for (int n = 0; n < 8; ++n)
            #pragma unroll
            for (int r = 0; r < 4; ++r) acc[m][n][r] = 0.f;

    // ---- cp.async staging: 128 threads x 4 segs each for A and B ----
    auto stage = [&](int chunk, int buf) {
        const int ko = chunk * BK;
        #pragma unroll
        for (int i = 0; i < 4; ++i) {
            const int x = t + i * 128;       // 0..511
            const int row = x >> 2, sg = x & 3;
            const uint32_t doff = (uint32_t)buf * TILEB
                                + (uint32_t)row * RSTRIDE + (uint32_t)sg * 16;
            cp16(sAu + doff, Abase + (size_t)row * DDIM + ko + sg * 8);
            cp16(sBu + doff, Bbase + (size_t)row * DDIM + ko + sg * 8);
        }
        CP_COMMIT();
    };

    stage(0, 0);

    #pragma unroll 1
    for (int chunk = 0; chunk < DDIM / BK; ++chunk) {
        const int buf = chunk & 1;
        if (chunk + 1 < DDIM / BK) {
            stage(chunk + 1, buf ^ 1);
            CP_WAIT(1);
        } else {
            CP_WAIT(0);
        }
        __syncthreads();    // buf filled & visible to all warps

        const uint32_t boff = (uint32_t)buf * TILEB;
        #pragma unroll
        for (int ks = 0; ks < 2; ++ks) {           // two k16 steps per chunk
            const uint32_t koff = boff + (uint32_t)(ks * 32);
            uint32_t af[4][4];
            #pragma unroll
            for (int m = 0; m < 4; ++m)
                ldsm4(af[m], aAddr + (uint32_t)(m * 16) * RSTRIDE + koff);
            uint32_t bf_[4][4];                    // pair p -> n-atoms 2p, 2p+1
            #pragma unroll
            for (int p = 0; p < 4; ++p)
                ldsm4(bf_[p], bAddr + (uint32_t)(p * 16) * RSTRIDE + koff);

            #pragma unroll
            for (int m = 0; m < 4; ++m)
                #pragma unroll
                for (int p = 0; p < 4; ++p) {
                    mma16816(acc[m][2 * p],     af[m], &bf_[p][0]);
                    mma16816(acc[m][2 * p + 1], af[m], &bf_[p][2]);
                }
        }
        __syncthreads();    // done reading buf before it is re-staged
    }

    // -------- fused epilogue: L2 -> sum of 5 Gaussian kernels --------
    const float negc2 = g_negc2;
    // C[row][col]: row = wrow + m*16 + (lane>>2) + 8*(r>>1)
    //              col = wcol + n*8 + (lane&3)*2 + (r&1)
    float sa[8], sb[16];
    #pragma unroll
    for (int m = 0; m < 4; ++m)
        #pragma unroll
        for (int h = 0; h < 2; ++h)
            sa[m * 2 + h] = sqa[wrow + m * 16 + (lane >> 2) + h * 8];
    #pragma unroll
    for (int n = 0; n < 8; ++n) {
        sb[n * 2 + 0] = sqb[wcol + n * 8 + (lane & 3) * 2 + 0];
        sb[n * 2 + 1] = sqb[wcol + n * 8 + (lane & 3) * 2 + 1];
    }

    float tsum = 0.f;
    #pragma unroll
    for (int m = 0; m < 4; ++m)
        #pragma unroll
        for (int n = 0; n < 8; ++n)
            #pragma unroll
            for (int r = 0; r < 4; ++r) {
                float d  = acc[m][n][r];
                float l2 = fmaf(-2.f, d, sa[m * 2 + (r >> 1)] + sb[n * 2 + (r & 1)]);
                float u  = fast_ex2(l2 * negc2);
                float u2 = u * u, u4 = u2 * u2, u8 = u4 * u4, u16 = u8 * u8;
                tsum += (u + u2) + (u4 + u8) + u16;
            }

    red[t] = tsum;
    __syncthreads();
    #pragma unroll
    for (int st = 64; st; st >>= 1) {
        if (t < st) red[t] += red[t + st];
        __syncthreads();
    }
    if (t == 0) {
        bool  si   = (ti * 128) < B;
        bool  sj   = (tj * 128) < B;
        float w    = (ti == tj) ? 1.f : 2.f;
        float sgnw = (si == sj) ? w : -w;
        atomicAdd(&g_accum, (double)(red[0] * sgnw));
    }
}

// ---------------------------------------------------------------------------
__global__ void k_final(float* out, int B) {
    out[0] = (float)(g_accum / ((double)B * (double)B));
}

// ---------------------------------------------------------------------------
extern "C" void kernel_launch(void* const* d_in, const int* in_sizes, int n_in,
                              void* d_out, int out_size) {
    const float* src = (const float*)d_in[0];
    const float* tgt = (const float*)d_in[1];
    const int B = in_sizes[0] / DDIM;   // 4096
    const int N = 2 * B;                // 8192
    const int NT = N / 128;             // 64 tiles per dim

    k_zero<<<1, 256>>>();
    k_prep<<<N / 64, 256>>>(src, tgt, B);
    k_bw<<<1, 256>>>(B);
    const int ntri = NT * (NT + 1) / 2; // 2080 upper-triangular tiles
    k_mmd<<<ntri, 128>>>(B, NT);
    k_final<<<1, 1>>>((float*)d_out, B);
}

// round 7
// speedup vs baseline: 5.4982x; 1.3228x over previous
#include <cuda_runtime.h>
#include <cuda_bf16.h>
#include <cstdint>
#include <math.h>

// MMD loss: B=4096, D=256, N=2B=8192.
// loss = (1/B^2) * sum_{i,j} sign(i,j) * K(i,j),  sign = +1 same block, -1 cross.
// K(i,j) = sum_{m=0..4} exp(-L2_ij / (bw*2^m)),  bw = (sum L2)/(N^2-N)/4.
// u = exp2(L2 * negc2) -> K = u+u^2+u^4+u^8+u^16.
// Gram matrix via mma.sync bf16. g_bf16 is stored CHUNK-CONTIGUOUS and
// PRE-SWIZZLED so each (tile, kchunk) stages with ONE cp.async.bulk per matrix.
// Layout: elem(row,c) -> (row>>7)*32768 + (c>>6)*8192 + (row&127)*64
//                        + (((c&63)>>3) ^ (row&7))*8 + (c&7)

#define DDIM 256
#define CHUNK_B 16384           // 128 rows x 64 bf16 x 2B, contiguous
#define TILE_B  65536           // 4 chunks

__device__ __nv_bfloat16 g_bf16[8192 * 256]; // swizzled chunked [src; tgt]
__device__ float  g_sq[8192];
__device__ float  g_colsum[256];
__device__ float  g_negc2;                   // -log2(e)/(16*bw)
__device__ double g_accum;

// SMEM layout (dynamic): [A0 16K][A1 16K][B0 16K][B1 16K][mbar 2x8][sqa][sqb][red]
#define SM_A(buf)  ((uint32_t)(buf) << 14)
#define SM_B(buf)  (32768u + ((uint32_t)(buf) << 14))
#define SM_MBAR    65536u
#define SM_SQA     65552u
#define SM_SQB     66064u
#define SM_RED     66576u
#define SM_TOTAL   67088

// ---------------- helpers ---------------------------------------------------
__device__ __forceinline__ uint32_t smem_u32(const void* p) {
    uint32_t a;
    asm("{ .reg .u64 t; cvta.to.shared.u64 t, %1; cvt.u32.u64 %0, t; }" : "=r"(a) : "l"(p));
    return a;
}
__device__ __forceinline__ void ldsm4(uint32_t* r, uint32_t addr) {
    asm volatile("ldmatrix.sync.aligned.m8n8.x4.shared.b16 {%0,%1,%2,%3}, [%4];"
                 : "=r"(r[0]), "=r"(r[1]), "=r"(r[2]), "=r"(r[3]) : "r"(addr));
}
__device__ __forceinline__ void mma16816(float* c, const uint32_t* a, const uint32_t* b) {
    asm volatile(
        "mma.sync.aligned.m16n8k16.row.col.f32.bf16.bf16.f32 "
        "{%0,%1,%2,%3}, {%4,%5,%6,%7}, {%8,%9}, {%0,%1,%2,%3};"
        : "+f"(c[0]), "+f"(c[1]), "+f"(c[2]), "+f"(c[3])
        : "r"(a[0]), "r"(a[1]), "r"(a[2]), "r"(a[3]), "r"(b[0]), "r"(b[1]));
}
__device__ __forceinline__ void bulk_g2s(uint32_t dst, const void* src,
                                         uint32_t bytes, uint32_t mbar) {
    asm volatile(
        "cp.async.bulk.shared::cluster.global.mbarrier::complete_tx::bytes [%0], [%1], %2, [%3];"
        :: "r"(dst), "l"(src), "r"(bytes), "r"(mbar) : "memory");
}
#define MB_INIT(mb, c) asm volatile("mbarrier.init.shared.b64 [%0], %1;" :: "r"(mb), "r"(c) : "memory")
#define MB_EXPECT_TX(mb, n) asm volatile("mbarrier.arrive.expect_tx.shared.b64 _, [%0], %1;" :: "r"(mb), "r"(n) : "memory")
#define MB_WAIT(mb, par) do {                                                 \
    uint32_t _m = (mb), _p = (par), _d;                                       \
    asm volatile("{\n\t.reg .pred p;\n\t"                                     \
        "mbarrier.try_wait.parity.acquire.cta.shared::cta.b64 p, [%1], %2;\n\t" \
        "selp.b32 %0, 1, 0, p;\n\t}" : "=r"(_d) : "r"(_m), "r"(_p) : "memory"); \
    if (!_d) {                                                                \
        asm volatile("{\n\t.reg .pred P1;\n\t"                                \
            "W_%=:\n\t"                                                       \
            "mbarrier.try_wait.parity.acquire.cta.shared::cta.b64 P1, [%0], %1, 0x989680;\n\t" \
            "@P1 bra.uni D_%=;\n\t"                                           \
            "bra.uni W_%=;\n\t"                                               \
            "D_%=:\n\t}" :: "r"(_m), "r"(_p) : "memory");                     \
    }                                                                         \
} while (0)

__device__ __forceinline__ float fast_ex2(float x) {
    float r;
    asm("ex2.approx.ftz.f32 %0, %1;" : "=f"(r) : "f"(x));
    return r;
}

// ---------------------------------------------------------------------------
__global__ void k_zero() {
    g_colsum[threadIdx.x] = 0.f;
    if (threadIdx.x == 0) g_accum = 0.0;
}

// ---------------------------------------------------------------------------
// Round to bf16 and write into the swizzled chunk-contiguous layout.
// Row sq-norms and column sums FROM THE ROUNDED values.
__global__ void k_prep(const float* __restrict__ src,
                       const float* __restrict__ tgt, int B) {
    __shared__ float scol[256];
    scol[threadIdx.x] = 0.f;
    __syncthreads();

    const int warp = threadIdx.x >> 5;
    const int lane = threadIdx.x & 31;
    const int rowBase = blockIdx.x * 64 + warp * 8;

    float c0 = 0.f, c1 = 0.f, c2 = 0.f, c3 = 0.f;
    float c4 = 0.f, c5 = 0.f, c6 = 0.f, c7 = 0.f;

    const int ca = lane * 4;        // cols for v0
    const int cb = 128 + lane * 4;  // cols for v1

    #pragma unroll
    for (int r = 0; r < 8; ++r) {
        const int row = rowBase + r;
        const float* rp = (row < B) ? (src + (size_t)row * DDIM)
                                    : (tgt + (size_t)(row - B) * DDIM);
        float4 v0 = *(const float4*)(rp + ca);
        float4 v1 = *(const float4*)(rp + cb);

        __nv_bfloat162 h0 = __floats2bfloat162_rn(v0.x, v0.y);
        __nv_bfloat162 h1 = __floats2bfloat162_rn(v0.z, v0.w);
        __nv_bfloat162 h2 = __floats2bfloat162_rn(v1.x, v1.y);
        __nv_bfloat162 h3 = __floats2bfloat162_rn(v1.z, v1.w);

        uint2 p0 = make_uint2(*(uint32_t*)&h0, *(uint32_t*)&h1);
        uint2 p1 = make_uint2(*(uint32_t*)&h2, *(uint32_t*)&h3);

        // swizzled chunk-contiguous addresses (element units)
        const int tOff = (row >> 7) * 32768;
        const int rl   = row & 127;
        const int rx   = rl & 7;
        size_t e0 = (size_t)tOff + (ca >> 6) * 8192 + rl * 64
                  + ((((ca & 63) >> 3) ^ rx) * 8) + (ca & 7);
        size_t e1 = (size_t)tOff + (cb >> 6) * 8192 + rl * 64
                  + ((((cb & 63) >> 3) ^ rx) * 8) + (cb & 7);
        *(uint2*)(g_bf16 + e0) = p0;
        *(uint2*)(g_bf16 + e1) = p1;

        float x0 = __low2float(h0), x1 = __high2float(h0);
        float x2 = __low2float(h1), x3 = __high2float(h1);
        float x4 = __low2float(h2), x5 = __high2float(h2);
        float x6 = __low2float(h3), x7 = __high2float(h3);

        float ss = x0*x0 + x1*x1 + x2*x2 + x3*x3 + x4*x4 + x5*x5 + x6*x6 + x7*x7;
        #pragma unroll
        for (int o = 16; o; o >>= 1) ss += __shfl_xor_sync(0xffffffffu, ss, o);
        if (lane == 0) g_sq[row] = ss;

        c0 += x0; c1 += x1; c2 += x2; c3 += x3;
        c4 += x4; c5 += x5; c6 += x6; c7 += x7;
    }

    atomicAdd(&scol[lane * 4 + 0], c0);
    atomicAdd(&scol[lane * 4 + 1], c1);
    atomicAdd(&scol[lane * 4 + 2], c2);
    atomicAdd(&scol[lane * 4 + 3], c3);
    atomicAdd(&scol[128 + lane * 4 + 0], c4);
    atomicAdd(&scol[128 + lane * 4 + 1], c5);
    atomicAdd(&scol[128 + lane * 4 + 2], c6);
    atomicAdd(&scol[128 + lane * 4 + 3], c7);
    __syncthreads();
    atomicAdd(&g_colsum[threadIdx.x], scol[threadIdx.x]);
}

// ---------------------------------------------------------------------------
__global__ void k_bw(int B) {
    const int N = 2 * B;
    __shared__ double sh[256];
    const int t = threadIdx.x;

    double s = 0.0;
    for (int i = t; i < N; i += 256) s += (double)g_sq[i];
    sh[t] = s;
    __syncthreads();
    for (int st = 128; st; st >>= 1) {
        if (t < st) sh[t] += sh[t + st];
        __syncthreads();
    }
    double sumsq = sh[0];
    __syncthreads();

    float c = g_colsum[t];
    sh[t] = (double)c * (double)c;
    __syncthreads();
    for (int st = 128; st; st >>= 1) {
        if (t < st) sh[t] += sh[t + st];
        __syncthreads();
    }
    if (t == 0) {
        double ssq   = sh[0];
        double sumL2 = 2.0 * (double)N * sumsq - 2.0 * ssq;
        double bw    = sumL2 / ((double)N * (double)N - (double)N);
        bw /= 4.0;  // KERNEL_MUL^(KERNEL_NUM//2) = 2^2
        g_negc2 = (float)(-1.4426950408889634 / (16.0 * bw));
        g_accum = 0.0;
    }
}

// ---------------------------------------------------------------------------
// 128x128 Gram tile per CTA; 4 warps (2x2), 64x64 each. K in 4 chunks of 64,
// double-buffered via cp.async.bulk + mbarrier. Fused Gaussian epilogue.
__global__ void __launch_bounds__(128, 2) k_mmd(int B, int NT) {
    extern __shared__ __align__(16) char smem[];
    const uint32_t sbase = smem_u32(smem);
    const int t = threadIdx.x;
    const int wid = t >> 5, lane = t & 31;

    // decode linear upper-triangular index -> (ti, tj), tj >= ti.
    const int idx = blockIdx.x;
    float fn = (float)NT + 0.5f;
    int ti = (int)(fn - sqrtf(fn * fn - 2.0f * (float)idx));
    while (ti * NT - (ti * (ti - 1)) / 2 > idx) --ti;
    while ((ti + 1) * NT - ((ti + 1) * ti) / 2 <= idx) ++ti;
    const int tj = ti + (idx - (ti * NT - (ti * (ti - 1)) / 2));

    if (t == 0) {
        MB_INIT(sbase + SM_MBAR, 1);
        MB_INIT(sbase + SM_MBAR + 8, 1);
    }
    if (t < 128) {
        *(float*)(smem + SM_SQA + t * 4) = g_sq[ti * 128 + t];
        *(float*)(smem + SM_SQB + t * 4) = g_sq[tj * 128 + t];
    }
    __syncthreads();

    const char* gA = (const char*)g_bf16 + (size_t)ti * TILE_B;
    const char* gB = (const char*)g_bf16 + (size_t)tj * TILE_B;

    // stage chunk kc into buffer buf (2 bulk copies, one mbarrier)
    auto stage = [&](int kc, int buf) {
        const uint32_t mb = sbase + SM_MBAR + (uint32_t)buf * 8;
        MB_EXPECT_TX(mb, 2 * CHUNK_B);
        bulk_g2s(sbase + SM_A(buf), gA + (size_t)kc * CHUNK_B, CHUNK_B, mb);
        bulk_g2s(sbase + SM_B(buf), gB + (size_t)kc * CHUNK_B, CHUNK_B, mb);
    };
    if (t == 0) { stage(0, 0); stage(1, 1); }

    // warp tile: rows (wid&1)*64, cols (wid>>1)*64
    const int wrow = (wid & 1) * 64;
    const int wcol = (wid >> 1) * 64;
    const uint32_t xr  = (uint32_t)(lane & 7);
    const uint32_t hiA = (uint32_t)(lane >> 4);          // 0..1
    const uint32_t hiB = (uint32_t)((lane >> 3) & 1);    // 0..1
    uint32_t aRowOff[4], bRowOff[4];
    #pragma unroll
    for (int m = 0; m < 4; ++m)
        aRowOff[m] = (uint32_t)(wrow + m * 16 + (lane & 15)) * 128;
    #pragma unroll
    for (int p = 0; p < 4; ++p)
        bRowOff[p] = (uint32_t)(wcol + (lane & 7) + ((lane >> 4) & 1) * 8 + p * 16) * 128;

    float acc[4][8][4];
    #pragma unroll
    for (int m = 0; m < 4; ++m)
        #pragma unroll
        for (int n = 0; n < 8; ++n)
            #pragma unroll
            for (int r = 0; r < 4; ++r) acc[m][n][r] = 0.f;

    #pragma unroll 1
    for (int c = 0; c < 4; ++c) {
        const int buf = c & 1;
        MB_WAIT(sbase + SM_MBAR + (uint32_t)buf * 8, (c >> 1) & 1);

        const uint32_t aB = sbase + SM_A(buf);
        const uint32_t bB = sbase + SM_B(buf);
        #pragma unroll
        for (int ks = 0; ks < 4; ++ks) {
            uint32_t af[4][4], bf_[4][4];
            const uint32_t sgA = ((uint32_t)(ks * 2) + hiA) ^ xr;
            const uint32_t sgB = ((uint32_t)(ks * 2) + hiB) ^ xr;
            #pragma unroll
            for (int m = 0; m < 4; ++m)
                ldsm4(af[m], aB + aRowOff[m] + (sgA << 4));
            #pragma unroll
            for (int p = 0; p < 4; ++p)
                ldsm4(bf_[p], bB + bRowOff[p] + (sgB << 4));

            #pragma unroll
            for (int m = 0; m < 4; ++m)
                #pragma unroll
                for (int p = 0; p < 4; ++p) {
                    mma16816(acc[m][2 * p],     af[m], &bf_[p][0]);
                    mma16816(acc[m][2 * p + 1], af[m], &bf_[p][2]);
                }
        }
        __syncthreads();                  // all warps done reading buf
        if (c + 2 < 4 && t == 0) stage(c + 2, buf);
    }

    // -------- fused epilogue: L2 -> sum of 5 Gaussian kernels --------
    const float negc2 = g_negc2;
    const float* sqa = (const float*)(smem + SM_SQA);
    const float* sqb = (const float*)(smem + SM_SQB);
    // C[row][col]: row = wrow + m*16 + (lane>>2) + 8*(r>>1)
    //              col = wcol + n*8 + (lane&3)*2 + (r&1)
    float sa[8], sb[16];
    #pragma unroll
    for (int m = 0; m < 4; ++m)
        #pragma unroll
        for (int h = 0; h < 2; ++h)
            sa[m * 2 + h] = sqa[wrow + m * 16 + (lane >> 2) + h * 8];
    #pragma unroll
    for (int n = 0; n < 8; ++n) {
        sb[n * 2 + 0] = sqb[wcol + n * 8 + (lane & 3) * 2 + 0];
        sb[n * 2 + 1] = sqb[wcol + n * 8 + (lane & 3) * 2 + 1];
    }

    float tsum = 0.f;
    #pragma unroll
    for (int m = 0; m < 4; ++m)
        #pragma unroll
        for (int n = 0; n < 8; ++n)
            #pragma unroll
            for (int r = 0; r < 4; ++r) {
                float d  = acc[m][n][r];
                float l2 = fmaf(-2.f, d, sa[m * 2 + (r >> 1)] + sb[n * 2 + (r & 1)]);
                float u  = fast_ex2(l2 * negc2);
                float u2 = u * u, u4 = u2 * u2, u8 = u4 * u4, u16 = u8 * u8;
                tsum += (u + u2) + (u4 + u8) + u16;
            }

    float* red = (float*)(smem + SM_RED);
    red[t] = tsum;
    __syncthreads();
    #pragma unroll
    for (int st = 64; st; st >>= 1) {
        if (t < st) red[t] += red[t + st];
        __syncthreads();
    }
    if (t == 0) {
        bool  si   = (ti * 128) < B;
        bool  sj   = (tj * 128) < B;
        float w    = (ti == tj) ? 1.f : 2.f;
        float sgnw = (si == sj) ? w : -w;
        atomicAdd(&g_accum, (double)(red[0] * sgnw));
    }
}

// ---------------------------------------------------------------------------
__global__ void k_final(float* out, int B) {
    out[0] = (float)(g_accum / ((double)B * (double)B));
}

// ---------------------------------------------------------------------------
extern "C" void kernel_launch(void* const* d_in, const int* in_sizes, int n_in,
                              void* d_out, int out_size) {
    const float* src = (const float*)d_in[0];
    const float* tgt = (const float*)d_in[1];
    const int B = in_sizes[0] / DDIM;   // 4096
    const int N = 2 * B;                // 8192
    const int NT = N / 128;             // 64 tiles per dim

    cudaFuncSetAttribute(k_mmd, cudaFuncAttributeMaxDynamicSharedMemorySize, SM_TOTAL);

    k_zero<<<1, 256>>>();
    k_prep<<<N / 64, 256>>>(src, tgt, B);
    k_bw<<<1, 256>>>(B);
    const int ntri = NT * (NT + 1) / 2; // 2080 upper-triangular tiles
    k_mmd<<<ntri, 128, SM_TOTAL>>>(B, NT);
    k_final<<<1, 1>>>((float*)d_out, B);
}